// round 6
// baseline (speedup 1.0000x reference)
#include <cuda_runtime.h>
#include <cstdint>

#define BB 128
#define TT 256
#define HH 512
#define G4 2048  // 4*H
#define NCTA 128
#define NCTA_DIR 64

// ---------------- scratch (device globals; no allocation allowed) ----------
__device__ float g_xproj[(size_t)2 * TT * BB * G4];  // [d][t][b][4H], scan order
__device__ float g_hout0[(size_t)2 * TT * BB * HH];  // layer-0 outputs [d][t][b][H]
__device__ float g_h[2][2][BB][HH];                  // [parity][d][b][h], tf32-pre-rounded
__device__ unsigned g_bars[2][32];                   // per-direction barrier counters (padded)

// ---------------- tf32 helpers --------------------------------------------
__device__ __forceinline__ uint32_t f2tf(float f) {
    uint32_t u;
    asm("cvt.rna.tf32.f32 %0, %1;" : "=r"(u) : "f"(f));  // round-to-nearest (unbiased)
    return u;
}

__device__ __forceinline__ void mma8(float* c, const uint32_t* a, const uint32_t* b) {
    asm volatile(
        "mma.sync.aligned.m16n8k8.row.col.f32.tf32.tf32.f32 "
        "{%0,%1,%2,%3}, {%4,%5,%6,%7}, {%8,%9}, {%0,%1,%2,%3};"
        : "+f"(c[0]), "+f"(c[1]), "+f"(c[2]), "+f"(c[3])
        : "r"(a[0]), "r"(a[1]), "r"(a[2]), "r"(a[3]), "r"(b[0]), "r"(b[1]));
}

__device__ __forceinline__ float sigm(float v) { return 1.0f / (1.0f + expf(-v)); }

__device__ __forceinline__ void bar_arrive_release(unsigned* ctr) {
    asm volatile("red.release.gpu.global.add.u32 [%0], %1;" ::"l"(ctr), "r"(1u)
                 : "memory");
}
__device__ __forceinline__ unsigned bar_poll_acquire(unsigned* ctr) {
    unsigned v;
    asm volatile("ld.acquire.gpu.global.u32 %0, [%1];" : "=r"(v) : "l"(ctr)
                 : "memory");
    return v;
}

// ---------------- init: zero h (both parities) and barriers -----------------
__global__ void init_state_kernel() {
    int idx = blockIdx.x * blockDim.x + threadIdx.x;
    if (idx < 64) ((unsigned*)g_bars)[idx] = 0u;
    float4 z = make_float4(0.f, 0.f, 0.f, 0.f);
    if (idx < 65536) reinterpret_cast<float4*>(&g_h[0][0][0][0])[idx] = z;
}

// ---------------- input-projection GEMM (unchanged, known-good) -------------
template <int LAYER>
__global__ void __launch_bounds__(256) xproj_kernel(const float* __restrict__ x,
                                                    const float* __restrict__ Wx_all,
                                                    const float* __restrict__ b_all) {
    const int d = blockIdx.z;
    const int n0 = blockIdx.x * 64;
    const int m0 = blockIdx.y * 64;
    const int tid = threadIdx.x;
    const int lane = tid & 31, wid = tid >> 5;
    const int wm = wid >> 1, wn = wid & 1;

    const float* Wx = Wx_all + (size_t)(LAYER * 2 + d) * HH * G4;

    __shared__ float As[64][68];
    __shared__ float Bs[64][72];

    float acc[4][4];
#pragma unroll
    for (int f = 0; f < 4; f++)
#pragma unroll
        for (int e = 0; e < 4; e++) acc[f][e] = 0.f;

    for (int k0 = 0; k0 < HH; k0 += 64) {
        __syncthreads();
#pragma unroll
        for (int r = 0; r < 4; r++) {
            int lin = r * 256 + tid;
            int row = lin >> 4;
            int kq = lin & 15;
            int rg = m0 + row;
            int tt = rg >> 7;
            int bb = rg & (BB - 1);
            const float* src;
            if (LAYER == 0) {
                int tsrc = d ? (TT - 1 - tt) : tt;
                src = x + ((size_t)bb * TT + tsrc) * HH + k0 + kq * 4;
            } else {
                src = g_hout0 + (((size_t)d * TT + tt) * BB + bb) * HH + k0 + kq * 4;
            }
            *(float4*)&As[row][kq * 4] = *(const float4*)src;
        }
#pragma unroll
        for (int r = 0; r < 4; r++) {
            int lin = r * 256 + tid;
            int kk = lin >> 4;
            int nq = lin & 15;
            *(float4*)&Bs[kk][nq * 4] =
                *(const float4*)&Wx[(size_t)(k0 + kk) * G4 + n0 + nq * 4];
        }
        __syncthreads();
#pragma unroll
        for (int kk = 0; kk < 64; kk += 8) {
            uint32_t af[4], bf[4][2];
            int row = wm * 16 + (lane >> 2);
            af[0] = f2tf(As[row][kk + (lane & 3)]);
            af[1] = f2tf(As[row + 8][kk + (lane & 3)]);
            af[2] = f2tf(As[row][kk + (lane & 3) + 4]);
            af[3] = f2tf(As[row + 8][kk + (lane & 3) + 4]);
#pragma unroll
            for (int f = 0; f < 4; f++) {
                int nn = wn * 32 + f * 8 + (lane >> 2);
                bf[f][0] = f2tf(Bs[kk + (lane & 3)][nn]);
                bf[f][1] = f2tf(Bs[kk + (lane & 3) + 4][nn]);
            }
#pragma unroll
            for (int f = 0; f < 4; f++) mma8(acc[f], af, bf[f]);
        }
    }
    const float* bias = b_all + (size_t)(LAYER * 2 + d) * G4;
#pragma unroll
    for (int f = 0; f < 4; f++) {
        int row = m0 + wm * 16 + (lane >> 2);
        int col = n0 + wn * 32 + f * 8 + 2 * (lane & 3);
        float b0v = bias[col], b1v = bias[col + 1];
        float* dst0 = g_xproj + ((size_t)d * TT * BB + row) * G4 + col;
        *(float2*)dst0 = make_float2(acc[f][0] + b0v, acc[f][1] + b1v);
        float* dst1 = g_xproj + ((size_t)d * TT * BB + row + 8) * G4 + col;
        *(float2*)dst1 = make_float2(acc[f][2] + b0v, acc[f][3] + b1v);
    }
}

// ---------------- persistent recurrence kernel ------------------------------
// 128 CTAs (64/dir). CTA = (dir d, 8 h-cols => 32 packed gate cols, all 128 b).
// Wh tile [512][32] resident in SMEM (tf32) for all 256 steps.
// R6: leader-only release/acquire per-direction barrier; 2-deep h prefetch;
// xproj slice prefetched into regs at step top; output stores after arrive.
// SMEM: WhS 512*36 u32 | Abuf 2*128*36 u32 (Gs overlays Abuf[0])
#define SM_WORDS (512 * 36 + 2 * 128 * 36)

template <int LAYER>
__global__ void __launch_bounds__(256, 1) lstm_persist_kernel(
    const float* __restrict__ Wh_all, float* __restrict__ out) {
    extern __shared__ uint32_t smem[];
    uint32_t* WhS = smem;                    // [512][36]
    uint32_t* Ab = smem + 512 * 36;          // [2][128][36]
    float* Gs = (float*)(smem + 512 * 36);   // overlay Abuf[0], [128][36]

    const int tid = threadIdx.x;
    const int lane = tid & 31, wid = tid >> 5;
    const int wm = wid >> 1, wn = wid & 1;
    const int d = blockIdx.x >> 6;
    const int h0 = (blockIdx.x & 63) * 8;

    const float* Wh = Wh_all + (size_t)(LAYER * 2 + d) * HH * G4;
    unsigned* ctr = &g_bars[d][0];

    // ---- load Wh tile once, converted to tf32, gate strips packed n=g*8+hc
    for (int lin = tid; lin < 4096; lin += 256) {
        int k = lin >> 3;
        int q = lin & 7;
        int g = q >> 1;
        int part = (q & 1) * 4;
        float4 v = *(const float4*)&Wh[(size_t)k * G4 + g * HH + h0 + part];
        uint32_t* dst = &WhS[k * 36 + g * 8 + part];
        dst[0] = f2tf(v.x);
        dst[1] = f2tf(v.y);
        dst[2] = f2tf(v.z);
        dst[3] = f2tf(v.w);
    }
    __syncthreads();

    // pointwise geometry (fixed per thread): 4 rows, 1 h-col
    const int phc = tid & 7;
    float c_reg[4] = {0.f, 0.f, 0.f, 0.f};

    for (int t = 0; t < TT; t++) {
        const float* hprev = &g_h[t & 1][d][0][0];
        const size_t xbase = ((size_t)d * TT * BB + (size_t)t * BB) * G4;

        // ---- prefetch this step's xproj slice into regs (hidden by GEMM)
        float xpv[4][4];
#pragma unroll
        for (int e = 0; e < 4; e++) {
            int row = (e * 256 + tid) >> 3;
            const float* xb = g_xproj + xbase + (size_t)row * G4 + h0 + phc;
            xpv[e][0] = __ldcg(xb);
            xpv[e][1] = __ldcg(xb + HH);
            xpv[e][2] = __ldcg(xb + 2 * HH);
            xpv[e][3] = __ldcg(xb + 3 * HH);
        }

        float acc[2][2][4];
#pragma unroll
        for (int mt = 0; mt < 2; mt++)
#pragma unroll
            for (int nt = 0; nt < 2; nt++)
#pragma unroll
                for (int e = 0; e < 4; e++) acc[mt][nt][e] = 0.f;

        // ---- 2-deep prefetch of h chunks (L1 bypass: parity addrs repeat)
        const int arow = tid >> 1;           // 128 rows / (256/2) -- wait: 2 loads/row
        float4 pre[2][4];
#pragma unroll
        for (int cc = 0; cc < 2; cc++)
#pragma unroll
            for (int j = 0; j < 4; j++) {
                int lin = j * 256 + tid;
                int row = lin >> 3, q = lin & 7;
                pre[cc][j] =
                    __ldcg((const float4*)&hprev[row * HH + cc * 32 + q * 4]);
            }
        // STS chunk 0
#pragma unroll
        for (int j = 0; j < 4; j++) {
            int lin = j * 256 + tid;
            int row = lin >> 3, q = lin & 7;
            *(float4*)&Ab[row * 36 + q * 4] = pre[0][j];
        }
        __syncthreads();

        for (int kc = 0; kc < 16; kc++) {
            // issue LDG for chunk kc+2 (2 mma phases of cover)
            if (kc + 2 < 16) {
#pragma unroll
                for (int j = 0; j < 4; j++) {
                    int lin = j * 256 + tid;
                    int row = lin >> 3, q = lin & 7;
                    pre[kc & 1][j] = __ldcg(
                        (const float4*)&hprev[row * HH + (kc + 2) * 32 + q * 4]);
                }
            }
            const uint32_t* Ac = &Ab[(kc & 1) * 128 * 36];
#pragma unroll
            for (int ks = 0; ks < 4; ks++) {
                uint32_t af[2][4], bfr[2][2];
                int ak = ks * 8 + (lane & 3);
                int ar = wm * 32 + (lane >> 2);
                af[0][0] = Ac[ar * 36 + ak];
                af[0][1] = Ac[(ar + 8) * 36 + ak];
                af[0][2] = Ac[ar * 36 + ak + 4];
                af[0][3] = Ac[(ar + 8) * 36 + ak + 4];
                af[1][0] = Ac[(ar + 16) * 36 + ak];
                af[1][1] = Ac[(ar + 24) * 36 + ak];
                af[1][2] = Ac[(ar + 16) * 36 + ak + 4];
                af[1][3] = Ac[(ar + 24) * 36 + ak + 4];
                int bk = kc * 32 + ks * 8 + (lane & 3);
                int bn = wn * 16 + (lane >> 2);
                bfr[0][0] = WhS[bk * 36 + bn];
                bfr[0][1] = WhS[(bk + 4) * 36 + bn];
                bfr[1][0] = WhS[bk * 36 + bn + 8];
                bfr[1][1] = WhS[(bk + 4) * 36 + bn + 8];
                mma8(acc[0][0], af[0], bfr[0]);
                mma8(acc[0][1], af[0], bfr[1]);
                mma8(acc[1][0], af[1], bfr[0]);
                mma8(acc[1][1], af[1], bfr[1]);
            }
            // STS chunk kc+1 into the other buffer
            if (kc + 1 < 16) {
#pragma unroll
                for (int j = 0; j < 4; j++) {
                    int lin = j * 256 + tid;
                    int row = lin >> 3, q = lin & 7;
                    *(float4*)&Ab[(((kc + 1) & 1) * 128 + row) * 36 + q * 4] =
                        pre[(kc + 1) & 1][j];
                }
            }
            __syncthreads();
        }

        // stage accumulators into Gs (Abuf[0]; last chunk kc=15 read Abuf[1])
#pragma unroll
        for (int mt = 0; mt < 2; mt++)
#pragma unroll
            for (int nt = 0; nt < 2; nt++) {
                int row = wm * 32 + mt * 16 + (lane >> 2);
                int col = wn * 16 + nt * 8 + 2 * (lane & 3);
                Gs[row * 36 + col] = acc[mt][nt][0];
                Gs[row * 36 + col + 1] = acc[mt][nt][1];
                Gs[(row + 8) * 36 + col] = acc[mt][nt][2];
                Gs[(row + 8) * 36 + col + 1] = acc[mt][nt][3];
            }
        __syncthreads();

        // fused pointwise; c in regs; write hnext (tf32-pre-rounded) first
        float* hnext = &g_h[(t + 1) & 1][d][0][0];
        float hnv[4];
        int prow[4];
#pragma unroll
        for (int e = 0; e < 4; e++) {
            int row = (e * 256 + tid) >> 3;
            prow[e] = row;
            float iv = Gs[row * 36 + phc] + xpv[e][0];
            float fv = Gs[row * 36 + 8 + phc] + xpv[e][1];
            float gv = Gs[row * 36 + 16 + phc] + xpv[e][2];
            float ov = Gs[row * 36 + 24 + phc] + xpv[e][3];
            float it = sigm(iv), ft = sigm(fv), gt = tanhf(gv), ot = sigm(ov);
            float cn = ft * c_reg[e] + it * gt;
            c_reg[e] = cn;
            float hn = ot * tanhf(cn);
            hnv[e] = hn;
            __stcg(&hnext[row * HH + h0 + phc], __uint_as_float(f2tf(hn)));
        }

        // barrier arrive (leader-only release; CG-style HB via syncthreads)
        __syncthreads();
        if (tid == 0) bar_arrive_release(ctr);

        // output stores off the inter-CTA critical path
#pragma unroll
        for (int e = 0; e < 4; e++) {
            int row = prow[e];
            if (LAYER == 0) {
                g_hout0[(((size_t)d * TT + t) * BB + row) * HH + h0 + phc] = hnv[e];
            } else {
                int torig = d ? (TT - 1 - t) : t;
                out[((size_t)row * TT + torig) * (2 * HH) + (size_t)d * HH + h0 +
                    phc] = hnv[e];
            }
        }

        // leader spin (acquire + backoff), then broadcast to CTA
        if (tid == 0) {
            unsigned target = (unsigned)NCTA_DIR * (unsigned)(t + 1);
            while (bar_poll_acquire(ctr) < target) __nanosleep(32);
        }
        __syncthreads();
    }
}

// ---------------- launch ----------------------------------------------------
extern "C" void kernel_launch(void* const* d_in, const int* in_sizes, int n_in,
                              void* d_out, int out_size) {
    const float* x = (const float*)d_in[0];   // [B, T, H]
    const float* Wx = (const float*)d_in[1];  // [L, 2, H, 4H]
    const float* Wh = (const float*)d_in[2];  // [L, 2, H, 4H]
    const float* b = (const float*)d_in[3];   // [L, 2, 4H]
    float* out = (float*)d_out;               // [B, T, 2H]

    const int smem_bytes = SM_WORDS * 4;  // 110592
    cudaFuncSetAttribute(lstm_persist_kernel<0>,
                         cudaFuncAttributeMaxDynamicSharedMemorySize, smem_bytes);
    cudaFuncSetAttribute(lstm_persist_kernel<1>,
                         cudaFuncAttributeMaxDynamicSharedMemorySize, smem_bytes);

    dim3 gx(G4 / 64, (TT * BB) / 64, 2);

    // ---- layer 0 ----
    xproj_kernel<0><<<gx, 256>>>(x, Wx, b);
    init_state_kernel<<<256, 256>>>();
    lstm_persist_kernel<0><<<NCTA, 256, smem_bytes>>>(Wh, nullptr);

    // ---- layer 1 ----
    xproj_kernel<1><<<gx, 256>>>(x, Wx, b);
    init_state_kernel<<<256, 256>>>();
    lstm_persist_kernel<1><<<NCTA, 256, smem_bytes>>>(Wh, out);
}

// round 7
// speedup vs baseline: 1.3849x; 1.3849x over previous
#include <cuda_runtime.h>
#include <cstdint>

#define BB 128
#define TT 256
#define HH 512
#define G4 2048  // 4*H
#define NCTA 128

// ---------------- scratch (device globals; no allocation allowed) ----------
__device__ float g_xproj[(size_t)2 * TT * BB * G4];  // [d][t][b][4H], scan order
__device__ float g_hout0[(size_t)2 * TT * BB * HH];  // layer-0 outputs [d][t][b][H]
__device__ float g_h[2][2][BB][HH];                  // [parity][d][b][h], tf32-pre-rounded
__device__ unsigned g_bar;                           // grid barrier counter

// ---------------- tf32 helpers --------------------------------------------
__device__ __forceinline__ uint32_t f2tf(float f) {
    uint32_t u;
    asm("cvt.rna.tf32.f32 %0, %1;" : "=r"(u) : "f"(f));  // round-to-nearest (unbiased)
    return u;
}

__device__ __forceinline__ void mma8(float* c, const uint32_t* a, const uint32_t* b) {
    asm volatile(
        "mma.sync.aligned.m16n8k8.row.col.f32.tf32.tf32.f32 "
        "{%0,%1,%2,%3}, {%4,%5,%6,%7}, {%8,%9}, {%0,%1,%2,%3};"
        : "+f"(c[0]), "+f"(c[1]), "+f"(c[2]), "+f"(c[3])
        : "r"(a[0]), "r"(a[1]), "r"(a[2]), "r"(a[3]), "r"(b[0]), "r"(b[1]));
}

__device__ __forceinline__ float sigm(float v) { return 1.0f / (1.0f + expf(-v)); }

__device__ __forceinline__ uint32_t smem_u32(const void* p) {
    uint32_t a;
    asm("{ .reg .u64 t; cvta.to.shared.u64 t, %1; cvt.u32.u64 %0, t; }"
        : "=r"(a) : "l"(p));
    return a;
}

// cp.async.cg: 16B, L1-bypass (L2-coherent with __stcg writers)
__device__ __forceinline__ void cp_async16(uint32_t dst, const void* src) {
    asm volatile("cp.async.cg.shared.global [%0], [%1], 16;" ::"r"(dst), "l"(src));
}
#define CP_COMMIT() asm volatile("cp.async.commit_group;" ::: "memory")
#define CP_WAIT0() asm volatile("cp.async.wait_group 0;" ::: "memory")
#define CP_WAIT1() asm volatile("cp.async.wait_group 1;" ::: "memory")

// ---------------- init: zero h (both parities) and barrier ------------------
__global__ void init_state_kernel() {
    int idx = blockIdx.x * blockDim.x + threadIdx.x;
    if (idx == 0) g_bar = 0;
    float4 z = make_float4(0.f, 0.f, 0.f, 0.f);
    if (idx < 65536) reinterpret_cast<float4*>(&g_h[0][0][0][0])[idx] = z;
}

// ---------------- input-projection GEMM (unchanged, known-good) -------------
template <int LAYER>
__global__ void __launch_bounds__(256) xproj_kernel(const float* __restrict__ x,
                                                    const float* __restrict__ Wx_all,
                                                    const float* __restrict__ b_all) {
    const int d = blockIdx.z;
    const int n0 = blockIdx.x * 64;
    const int m0 = blockIdx.y * 64;
    const int tid = threadIdx.x;
    const int lane = tid & 31, wid = tid >> 5;
    const int wm = wid >> 1, wn = wid & 1;

    const float* Wx = Wx_all + (size_t)(LAYER * 2 + d) * HH * G4;

    __shared__ float As[64][68];
    __shared__ float Bs[64][72];

    float acc[4][4];
#pragma unroll
    for (int f = 0; f < 4; f++)
#pragma unroll
        for (int e = 0; e < 4; e++) acc[f][e] = 0.f;

    for (int k0 = 0; k0 < HH; k0 += 64) {
        __syncthreads();
#pragma unroll
        for (int r = 0; r < 4; r++) {
            int lin = r * 256 + tid;
            int row = lin >> 4;
            int kq = lin & 15;
            int rg = m0 + row;
            int tt = rg >> 7;
            int bb = rg & (BB - 1);
            const float* src;
            if (LAYER == 0) {
                int tsrc = d ? (TT - 1 - tt) : tt;
                src = x + ((size_t)bb * TT + tsrc) * HH + k0 + kq * 4;
            } else {
                src = g_hout0 + (((size_t)d * TT + tt) * BB + bb) * HH + k0 + kq * 4;
            }
            *(float4*)&As[row][kq * 4] = *(const float4*)src;
        }
#pragma unroll
        for (int r = 0; r < 4; r++) {
            int lin = r * 256 + tid;
            int kk = lin >> 4;
            int nq = lin & 15;
            *(float4*)&Bs[kk][nq * 4] =
                *(const float4*)&Wx[(size_t)(k0 + kk) * G4 + n0 + nq * 4];
        }
        __syncthreads();
#pragma unroll
        for (int kk = 0; kk < 64; kk += 8) {
            uint32_t af[4], bf[4][2];
            int row = wm * 16 + (lane >> 2);
            af[0] = f2tf(As[row][kk + (lane & 3)]);
            af[1] = f2tf(As[row + 8][kk + (lane & 3)]);
            af[2] = f2tf(As[row][kk + (lane & 3) + 4]);
            af[3] = f2tf(As[row + 8][kk + (lane & 3) + 4]);
#pragma unroll
            for (int f = 0; f < 4; f++) {
                int nn = wn * 32 + f * 8 + (lane >> 2);
                bf[f][0] = f2tf(Bs[kk + (lane & 3)][nn]);
                bf[f][1] = f2tf(Bs[kk + (lane & 3) + 4][nn]);
            }
#pragma unroll
            for (int f = 0; f < 4; f++) mma8(acc[f], af, bf[f]);
        }
    }
    const float* bias = b_all + (size_t)(LAYER * 2 + d) * G4;
#pragma unroll
    for (int f = 0; f < 4; f++) {
        int row = m0 + wm * 16 + (lane >> 2);
        int col = n0 + wn * 32 + f * 8 + 2 * (lane & 3);
        float b0v = bias[col], b1v = bias[col + 1];
        float* dst0 = g_xproj + ((size_t)d * TT * BB + row) * G4 + col;
        *(float2*)dst0 = make_float2(acc[f][0] + b0v, acc[f][1] + b1v);
        float* dst1 = g_xproj + ((size_t)d * TT * BB + row + 8) * G4 + col;
        *(float2*)dst1 = make_float2(acc[f][2] + b0v, acc[f][3] + b1v);
    }
}

// ---------------- persistent recurrence kernel ------------------------------
// 128 CTAs (64/dir). CTA = (dir d, 8 h-cols => 32 packed gate cols, all 128 b).
// Wh tile [512][40] resident in SMEM (tf32; stride 40 -> conflict-free B frags).
// R7: A (h_prev) fed via cp.async.cg in 4 K-chunks of 128 (2 buffers,
// [128][132] each; pad 132 -> conflict-free A frags). No registers in the A
// path, copy latency covered by a full chunk of mma, 9 syncthreads/step.
// Pointwise / gate staging / barrier identical to R5.
#define WH_STRIDE 40
#define PA 132
#define AB_OFF (512 * WH_STRIDE)                  // words
#define AB_WORDS (128 * PA)                       // per buffer
#define SM_WORDS (AB_OFF + 2 * AB_WORDS)          // 20480 + 33792 = 54272 words

template <int LAYER>
__global__ void __launch_bounds__(256, 1) lstm_persist_kernel(
    const float* __restrict__ Wh_all, float* __restrict__ out) {
    extern __shared__ uint32_t smw[];
    uint32_t* WhS = smw;                          // [512][40]
    uint32_t* Ab = smw + AB_OFF;                  // [2][128][132]
    float* Gs = (float*)(smw + AB_OFF);           // overlay buf0, [128][40]
    const uint32_t sbase = smem_u32(smw);

    const int tid = threadIdx.x;
    const int lane = tid & 31, wid = tid >> 5;
    const int wm = wid >> 1, wn = wid & 1;
    const int d = blockIdx.x >> 6;
    const int h0 = (blockIdx.x & 63) * 8;

    const float* Wh = Wh_all + (size_t)(LAYER * 2 + d) * HH * G4;

    // ---- load Wh tile once, converted to tf32, gate strips packed n=g*8+hc
    for (int lin = tid; lin < 4096; lin += 256) {
        int k = lin >> 3;
        int q = lin & 7;
        int g = q >> 1;
        int part = (q & 1) * 4;
        float4 v = *(const float4*)&Wh[(size_t)k * G4 + g * HH + h0 + part];
        uint32_t* dst = &WhS[k * WH_STRIDE + g * 8 + part];
        dst[0] = f2tf(v.x);
        dst[1] = f2tf(v.y);
        dst[2] = f2tf(v.z);
        dst[3] = f2tf(v.w);
    }
    __syncthreads();

    const int phc = tid & 7;
    float c_reg[4] = {0.f, 0.f, 0.f, 0.f};

    for (int t = 0; t < TT; t++) {
        const float* hprev = &g_h[t & 1][d][0][0];

        float acc[2][2][4];
#pragma unroll
        for (int mt = 0; mt < 2; mt++)
#pragma unroll
            for (int nt = 0; nt < 2; nt++)
#pragma unroll
                for (int e = 0; e < 4; e++) acc[mt][nt][e] = 0.f;

        // ---- prologue: async-copy chunks 0 and 1
#pragma unroll
        for (int cc = 0; cc < 2; cc++) {
#pragma unroll
            for (int w = 0; w < 16; w++) {
                int p = w * 256 + tid;
                int row = p >> 5, kq = p & 31;
                uint32_t dst = sbase + (AB_OFF + cc * AB_WORDS + row * PA + kq * 4) * 4;
                cp_async16(dst, &hprev[(size_t)row * HH + cc * 128 + kq * 4]);
            }
            CP_COMMIT();
        }

#pragma unroll
        for (int c = 0; c < 4; c++) {
            if (c < 3) { CP_WAIT1(); } else { CP_WAIT0(); }
            __syncthreads();
            const uint32_t* Ac = &Ab[(c & 1) * AB_WORDS];
#pragma unroll
            for (int ks = 0; ks < 16; ks++) {
                uint32_t af[2][4], bfr[2][2];
                int ak = ks * 8 + (lane & 3);
                int ar = wm * 32 + (lane >> 2);
                af[0][0] = Ac[ar * PA + ak];
                af[0][1] = Ac[(ar + 8) * PA + ak];
                af[0][2] = Ac[ar * PA + ak + 4];
                af[0][3] = Ac[(ar + 8) * PA + ak + 4];
                af[1][0] = Ac[(ar + 16) * PA + ak];
                af[1][1] = Ac[(ar + 24) * PA + ak];
                af[1][2] = Ac[(ar + 16) * PA + ak + 4];
                af[1][3] = Ac[(ar + 24) * PA + ak + 4];
                int bk = c * 128 + ks * 8 + (lane & 3);
                int bn = wn * 16 + (lane >> 2);
                bfr[0][0] = WhS[bk * WH_STRIDE + bn];
                bfr[0][1] = WhS[(bk + 4) * WH_STRIDE + bn];
                bfr[1][0] = WhS[bk * WH_STRIDE + bn + 8];
                bfr[1][1] = WhS[(bk + 4) * WH_STRIDE + bn + 8];
                mma8(acc[0][0], af[0], bfr[0]);
                mma8(acc[0][1], af[0], bfr[1]);
                mma8(acc[1][0], af[1], bfr[0]);
                mma8(acc[1][1], af[1], bfr[1]);
            }
            __syncthreads();  // all warps done reading buf (c&1)
            if (c + 2 < 4) {
#pragma unroll
                for (int w = 0; w < 16; w++) {
                    int p = w * 256 + tid;
                    int row = p >> 5, kq = p & 31;
                    uint32_t dst =
                        sbase + (AB_OFF + (c & 1) * AB_WORDS + row * PA + kq * 4) * 4;
                    cp_async16(dst,
                               &hprev[(size_t)row * HH + (c + 2) * 128 + kq * 4]);
                }
                CP_COMMIT();
            }
        }

        // stage accumulators into Gs (buf0 region; last chunk read buf1)
#pragma unroll
        for (int mt = 0; mt < 2; mt++)
#pragma unroll
            for (int nt = 0; nt < 2; nt++) {
                int row = wm * 32 + mt * 16 + (lane >> 2);
                int col = wn * 16 + nt * 8 + 2 * (lane & 3);
                Gs[row * 40 + col] = acc[mt][nt][0];
                Gs[row * 40 + col + 1] = acc[mt][nt][1];
                Gs[(row + 8) * 40 + col] = acc[mt][nt][2];
                Gs[(row + 8) * 40 + col + 1] = acc[mt][nt][3];
            }
        __syncthreads();

        // fused pointwise; c in registers; h stored tf32-pre-rounded
        const size_t xbase = ((size_t)d * TT * BB + (size_t)t * BB) * G4;
        float* hnext = &g_h[(t + 1) & 1][d][0][0];
#pragma unroll
        for (int e = 0; e < 4; e++) {
            int row = (e * 256 + tid) >> 3;
            const float* xp = g_xproj + xbase + (size_t)row * G4 + h0 + phc;
            float iv = Gs[row * 40 + phc] + xp[0];
            float fv = Gs[row * 40 + 8 + phc] + xp[HH];
            float gv = Gs[row * 40 + 16 + phc] + xp[2 * HH];
            float ov = Gs[row * 40 + 24 + phc] + xp[3 * HH];
            float it = sigm(iv), ft = sigm(fv), gt = tanhf(gv), ot = sigm(ov);
            float cn = ft * c_reg[e] + it * gt;
            c_reg[e] = cn;
            float hn = ot * tanhf(cn);
            __stcg(&hnext[row * HH + h0 + phc], __uint_as_float(f2tf(hn)));
            if (LAYER == 0) {
                g_hout0[(((size_t)d * TT + t) * BB + row) * HH + h0 + phc] = hn;
            } else {
                int torig = d ? (TT - 1 - t) : t;
                out[((size_t)row * TT + torig) * (2 * HH) + (size_t)d * HH + h0 +
                    phc] = hn;
            }
        }

        // grid-wide barrier (R5 verbatim): release h writes, arrive + spin
        __threadfence();
        __syncthreads();
        if (tid == 0) {
            atomicAdd(&g_bar, 1u);
            unsigned target = (unsigned)NCTA * (unsigned)(t + 1);
            while (*(volatile unsigned*)&g_bar < target) {
            }
            __threadfence();
        }
        __syncthreads();
    }
}

// ---------------- launch ----------------------------------------------------
extern "C" void kernel_launch(void* const* d_in, const int* in_sizes, int n_in,
                              void* d_out, int out_size) {
    const float* x = (const float*)d_in[0];   // [B, T, H]
    const float* Wx = (const float*)d_in[1];  // [L, 2, H, 4H]
    const float* Wh = (const float*)d_in[2];  // [L, 2, H, 4H]
    const float* b = (const float*)d_in[3];   // [L, 2, 4H]
    float* out = (float*)d_out;               // [B, T, 2H]

    const int smem_bytes = SM_WORDS * 4;  // 217088
    cudaFuncSetAttribute(lstm_persist_kernel<0>,
                         cudaFuncAttributeMaxDynamicSharedMemorySize, smem_bytes);
    cudaFuncSetAttribute(lstm_persist_kernel<1>,
                         cudaFuncAttributeMaxDynamicSharedMemorySize, smem_bytes);

    dim3 gx(G4 / 64, (TT * BB) / 64, 2);

    // ---- layer 0 ----
    xproj_kernel<0><<<gx, 256>>>(x, Wx, b);
    init_state_kernel<<<256, 256>>>();
    lstm_persist_kernel<0><<<NCTA, 256, smem_bytes>>>(Wh, nullptr);

    // ---- layer 1 ----
    xproj_kernel<1><<<gx, 256>>>(x, Wx, b);
    init_state_kernel<<<256, 256>>>();
    lstm_persist_kernel<1><<<NCTA, 256, smem_bytes>>>(Wh, out);
}

// round 8
// speedup vs baseline: 1.4761x; 1.0659x over previous
#include <cuda_runtime.h>
#include <cstdint>

#define BB 128
#define TT 256
#define HH 512
#define G4 2048  // 4*H
#define NCTA 128

// ---------------- scratch (device globals; no allocation allowed) ----------
__device__ float g_xproj[(size_t)2 * TT * BB * G4];  // [d][t][b][4H], scan order
__device__ float g_hout0[(size_t)2 * TT * BB * HH];  // layer-0 outputs [d][t][b][H]
__device__ float g_h[2][2][BB][HH];                  // [parity][d][b][h], tf32-pre-rounded
__device__ unsigned g_bar;                           // grid barrier counter

// ---------------- tf32 helpers --------------------------------------------
__device__ __forceinline__ uint32_t f2tf(float f) {
    uint32_t u;
    asm("cvt.rna.tf32.f32 %0, %1;" : "=r"(u) : "f"(f));  // round-to-nearest (unbiased)
    return u;
}

__device__ __forceinline__ void mma8(float* c, const uint32_t* a, const uint32_t* b) {
    asm volatile(
        "mma.sync.aligned.m16n8k8.row.col.f32.tf32.tf32.f32 "
        "{%0,%1,%2,%3}, {%4,%5,%6,%7}, {%8,%9}, {%0,%1,%2,%3};"
        : "+f"(c[0]), "+f"(c[1]), "+f"(c[2]), "+f"(c[3])
        : "r"(a[0]), "r"(a[1]), "r"(a[2]), "r"(a[3]), "r"(b[0]), "r"(b[1]));
}

__device__ __forceinline__ float sigm(float v) { return 1.0f / (1.0f + expf(-v)); }

__device__ __forceinline__ uint32_t smem_u32(const void* p) {
    uint32_t a;
    asm("{ .reg .u64 t; cvta.to.shared.u64 t, %1; cvt.u32.u64 %0, t; }"
        : "=r"(a) : "l"(p));
    return a;
}

// cp.async.cg: 16B, L1-bypass (L2-coherent with __stcg writers)
__device__ __forceinline__ void cp_async16(uint32_t dst, const void* src) {
    asm volatile("cp.async.cg.shared.global [%0], [%1], 16;" ::"r"(dst), "l"(src));
}
#define CP_COMMIT() asm volatile("cp.async.commit_group;" ::: "memory")
#define CP_WAIT0() asm volatile("cp.async.wait_group 0;" ::: "memory")
#define CP_WAIT1() asm volatile("cp.async.wait_group 1;" ::: "memory")

// ---------------- init: zero h (both parities) and barrier ------------------
__global__ void init_state_kernel() {
    int idx = blockIdx.x * blockDim.x + threadIdx.x;
    if (idx == 0) g_bar = 0;
    float4 z = make_float4(0.f, 0.f, 0.f, 0.f);
    if (idx < 65536) reinterpret_cast<float4*>(&g_h[0][0][0][0])[idx] = z;
}

// no-op: shifts stream launch index so ncu (-s 5) samples the persistent kernel
__global__ void profile_anchor_kernel() {}

// ---------------- input-projection GEMM (unchanged, known-good) -------------
template <int LAYER>
__global__ void __launch_bounds__(256) xproj_kernel(const float* __restrict__ x,
                                                    const float* __restrict__ Wx_all,
                                                    const float* __restrict__ b_all) {
    const int d = blockIdx.z;
    const int n0 = blockIdx.x * 64;
    const int m0 = blockIdx.y * 64;
    const int tid = threadIdx.x;
    const int lane = tid & 31, wid = tid >> 5;
    const int wm = wid >> 1, wn = wid & 1;

    const float* Wx = Wx_all + (size_t)(LAYER * 2 + d) * HH * G4;

    __shared__ float As[64][68];
    __shared__ float Bs[64][72];

    float acc[4][4];
#pragma unroll
    for (int f = 0; f < 4; f++)
#pragma unroll
        for (int e = 0; e < 4; e++) acc[f][e] = 0.f;

    for (int k0 = 0; k0 < HH; k0 += 64) {
        __syncthreads();
#pragma unroll
        for (int r = 0; r < 4; r++) {
            int lin = r * 256 + tid;
            int row = lin >> 4;
            int kq = lin & 15;
            int rg = m0 + row;
            int tt = rg >> 7;
            int bb = rg & (BB - 1);
            const float* src;
            if (LAYER == 0) {
                int tsrc = d ? (TT - 1 - tt) : tt;
                src = x + ((size_t)bb * TT + tsrc) * HH + k0 + kq * 4;
            } else {
                src = g_hout0 + (((size_t)d * TT + tt) * BB + bb) * HH + k0 + kq * 4;
            }
            *(float4*)&As[row][kq * 4] = *(const float4*)src;
        }
#pragma unroll
        for (int r = 0; r < 4; r++) {
            int lin = r * 256 + tid;
            int kk = lin >> 4;
            int nq = lin & 15;
            *(float4*)&Bs[kk][nq * 4] =
                *(const float4*)&Wx[(size_t)(k0 + kk) * G4 + n0 + nq * 4];
        }
        __syncthreads();
#pragma unroll
        for (int kk = 0; kk < 64; kk += 8) {
            uint32_t af[4], bf[4][2];
            int row = wm * 16 + (lane >> 2);
            af[0] = f2tf(As[row][kk + (lane & 3)]);
            af[1] = f2tf(As[row + 8][kk + (lane & 3)]);
            af[2] = f2tf(As[row][kk + (lane & 3) + 4]);
            af[3] = f2tf(As[row + 8][kk + (lane & 3) + 4]);
#pragma unroll
            for (int f = 0; f < 4; f++) {
                int nn = wn * 32 + f * 8 + (lane >> 2);
                bf[f][0] = f2tf(Bs[kk + (lane & 3)][nn]);
                bf[f][1] = f2tf(Bs[kk + (lane & 3) + 4][nn]);
            }
#pragma unroll
            for (int f = 0; f < 4; f++) mma8(acc[f], af, bf[f]);
        }
    }
    const float* bias = b_all + (size_t)(LAYER * 2 + d) * G4;
#pragma unroll
    for (int f = 0; f < 4; f++) {
        int row = m0 + wm * 16 + (lane >> 2);
        int col = n0 + wn * 32 + f * 8 + 2 * (lane & 3);
        float b0v = bias[col], b1v = bias[col + 1];
        float* dst0 = g_xproj + ((size_t)d * TT * BB + row) * G4 + col;
        *(float2*)dst0 = make_float2(acc[f][0] + b0v, acc[f][1] + b1v);
        float* dst1 = g_xproj + ((size_t)d * TT * BB + row + 8) * G4 + col;
        *(float2*)dst1 = make_float2(acc[f][2] + b0v, acc[f][3] + b1v);
    }
}

// ---------------- persistent recurrence kernel ------------------------------
// 128 CTAs (64/dir). CTA = (dir d, 8 h-cols => 32 packed gate cols, all 128 b).
// R8: 512 threads / 16 warps. K=512 reduction split across two warp groups
// (wk=0: K 0..255, wk=1: K 256..511), same m32n16 warp tiles -> per-warp mma
// chain and LDS halve; 4 warps/SMSP hide LDS/HMMA/L2 latency.
// A feed: 8 chunks of 64 K via cp.async in 4 paired commit groups over 4
// buffers [128][68]. Partial accs staged to Gs0/Gs1 (overlay buf0/buf1, free
// at staging time) and summed in the pointwise.
#define WH_STRIDE 40
#define PAC 68
#define ABW (128 * PAC)                       // words per buffer (8704)
#define AB_OFF (512 * WH_STRIDE)              // 20480 words
#define SM_WORDS (AB_OFF + 4 * ABW)           // 55296 words = 221184 B

template <int LAYER>
__global__ void __launch_bounds__(512, 1) lstm_persist_kernel(
    const float* __restrict__ Wh_all, float* __restrict__ out) {
    extern __shared__ uint32_t smw[];
    uint32_t* WhS = smw;                      // [512][40]
    uint32_t* Ab = smw + AB_OFF;              // [4][128][68]
    float* Gs0 = (float*)(smw + AB_OFF);              // overlay buf0, [128][40]
    float* Gs1 = (float*)(smw + AB_OFF + ABW);        // overlay buf1, [128][40]
    const uint32_t sbase = smem_u32(smw);

    const int tid = threadIdx.x;
    const int lane = tid & 31, wid = tid >> 5;
    const int wk = wid >> 3;          // K-half (0: k<256, 1: k>=256)
    const int wt = wid & 7;           // warp tile
    const int wm = wt >> 1, wn = wt & 1;
    const int d = blockIdx.x >> 6;
    const int h0 = (blockIdx.x & 63) * 8;

    const float* Wh = Wh_all + (size_t)(LAYER * 2 + d) * HH * G4;

    // ---- load Wh tile once, converted to tf32, gate strips packed n=g*8+hc
    for (int lin = tid; lin < 4096; lin += 512) {
        int k = lin >> 3;
        int q = lin & 7;
        int g = q >> 1;
        int part = (q & 1) * 4;
        float4 v = *(const float4*)&Wh[(size_t)k * G4 + g * HH + h0 + part];
        uint32_t* dst = &WhS[k * WH_STRIDE + g * 8 + part];
        dst[0] = f2tf(v.x);
        dst[1] = f2tf(v.y);
        dst[2] = f2tf(v.z);
        dst[3] = f2tf(v.w);
    }
    __syncthreads();

    const int phc = tid & 7;
    float c_reg[2] = {0.f, 0.f};

    for (int t = 0; t < TT; t++) {
        const float* hprev = &g_h[t & 1][d][0][0];

        float acc[2][2][4];
#pragma unroll
        for (int mt = 0; mt < 2; mt++)
#pragma unroll
            for (int nt = 0; nt < 2; nt++)
#pragma unroll
                for (int e = 0; e < 4; e++) acc[mt][nt][e] = 0.f;

        // ---- prologue: G0 = {chunk0->buf0, chunk4->buf1}, G1 = {1->buf2, 5->buf3}
#pragma unroll
        for (int gph = 0; gph < 2; gph++) {       // gph: chunks (gph, gph+4)
#pragma unroll
            for (int half = 0; half < 2; half++) {  // half 0: low-K chunk, 1: high-K
                int ck = gph + half * 4;
                int bufi = gph * 2 + half;
#pragma unroll
                for (int w = 0; w < 4; w++) {
                    int p = w * 512 + tid;
                    int row = p >> 4, kq = p & 15;
                    uint32_t dst =
                        sbase + (AB_OFF + bufi * ABW + row * PAC + kq * 4) * 4;
                    cp_async16(dst, &hprev[(size_t)row * HH + ck * 64 + kq * 4]);
                }
            }
            CP_COMMIT();
        }

        // ---- 4 phases; phase p: wk0 computes chunk p, wk1 computes chunk p+4
#pragma unroll
        for (int p = 0; p < 4; p++) {
            if (p < 3) { CP_WAIT1(); } else { CP_WAIT0(); }
            __syncthreads();
            const uint32_t* Ac = &Ab[(((2 * p) & 3) + wk) * ABW];
            const int kb = wk * 256 + p * 64;
#pragma unroll
            for (int ks = 0; ks < 8; ks++) {
                uint32_t af[2][4], bfr[2][2];
                int ak = ks * 8 + (lane & 3);
                int ar = wm * 32 + (lane >> 2);
                af[0][0] = Ac[ar * PAC + ak];
                af[0][1] = Ac[(ar + 8) * PAC + ak];
                af[0][2] = Ac[ar * PAC + ak + 4];
                af[0][3] = Ac[(ar + 8) * PAC + ak + 4];
                af[1][0] = Ac[(ar + 16) * PAC + ak];
                af[1][1] = Ac[(ar + 24) * PAC + ak];
                af[1][2] = Ac[(ar + 16) * PAC + ak + 4];
                af[1][3] = Ac[(ar + 24) * PAC + ak + 4];
                int bk = kb + ks * 8 + (lane & 3);
                int bn = wn * 16 + (lane >> 2);
                bfr[0][0] = WhS[bk * WH_STRIDE + bn];
                bfr[0][1] = WhS[(bk + 4) * WH_STRIDE + bn];
                bfr[1][0] = WhS[bk * WH_STRIDE + bn + 8];
                bfr[1][1] = WhS[(bk + 4) * WH_STRIDE + bn + 8];
                mma8(acc[0][0], af[0], bfr[0]);
                mma8(acc[0][1], af[0], bfr[1]);
                mma8(acc[1][0], af[1], bfr[0]);
                mma8(acc[1][1], af[1], bfr[1]);
            }
            __syncthreads();  // all warps done reading this phase's buffers
            if (p < 2) {
                int b0 = (2 * p) & 3;  // buffers just freed by this phase
#pragma unroll
                for (int half = 0; half < 2; half++) {
                    int ck = (p + 2) + half * 4;
#pragma unroll
                    for (int w = 0; w < 4; w++) {
                        int q = w * 512 + tid;
                        int row = q >> 4, kq = q & 15;
                        uint32_t dst =
                            sbase +
                            (AB_OFF + (b0 + half) * ABW + row * PAC + kq * 4) * 4;
                        cp_async16(dst,
                                   &hprev[(size_t)row * HH + ck * 64 + kq * 4]);
                    }
                }
                CP_COMMIT();
            }
        }

        // ---- stage partial accs: wk0 -> Gs0 (buf0), wk1 -> Gs1 (buf1).
        // Phase 3 read buf2/buf3, so buf0/buf1 are free here.
        float* Gsw = wk ? Gs1 : Gs0;
#pragma unroll
        for (int mt = 0; mt < 2; mt++)
#pragma unroll
            for (int nt = 0; nt < 2; nt++) {
                int row = wm * 32 + mt * 16 + (lane >> 2);
                int col = wn * 16 + nt * 8 + 2 * (lane & 3);
                Gsw[row * 40 + col] = acc[mt][nt][0];
                Gsw[row * 40 + col + 1] = acc[mt][nt][1];
                Gsw[(row + 8) * 40 + col] = acc[mt][nt][2];
                Gsw[(row + 8) * 40 + col + 1] = acc[mt][nt][3];
            }
        __syncthreads();

        // ---- fused pointwise; sum K-halves; c in regs; h tf32-pre-rounded
        const size_t xbase = ((size_t)d * TT * BB + (size_t)t * BB) * G4;
        float* hnext = &g_h[(t + 1) & 1][d][0][0];
#pragma unroll
        for (int e = 0; e < 2; e++) {
            int row = e * 64 + (tid >> 3);
            const float* xp = g_xproj + xbase + (size_t)row * G4 + h0 + phc;
            float iv = Gs0[row * 40 + phc] + Gs1[row * 40 + phc] + xp[0];
            float fv = Gs0[row * 40 + 8 + phc] + Gs1[row * 40 + 8 + phc] + xp[HH];
            float gv =
                Gs0[row * 40 + 16 + phc] + Gs1[row * 40 + 16 + phc] + xp[2 * HH];
            float ov =
                Gs0[row * 40 + 24 + phc] + Gs1[row * 40 + 24 + phc] + xp[3 * HH];
            float it = sigm(iv), ft = sigm(fv), gt = tanhf(gv), ot = sigm(ov);
            float cn = ft * c_reg[e] + it * gt;
            c_reg[e] = cn;
            float hn = ot * tanhf(cn);
            __stcg(&hnext[row * HH + h0 + phc], __uint_as_float(f2tf(hn)));
            if (LAYER == 0) {
                g_hout0[(((size_t)d * TT + t) * BB + row) * HH + h0 + phc] = hn;
            } else {
                int torig = d ? (TT - 1 - t) : t;
                out[((size_t)row * TT + torig) * (2 * HH) + (size_t)d * HH + h0 +
                    phc] = hn;
            }
        }

        // ---- grid barrier: CG-style leader release/spin (16 warps would make
        // the all-thread membar costly)
        __syncthreads();
        if (tid == 0) {
            __threadfence();
            atomicAdd(&g_bar, 1u);
            unsigned target = (unsigned)NCTA * (unsigned)(t + 1);
            while (*(volatile unsigned*)&g_bar < target) {
            }
            __threadfence();
        }
        __syncthreads();
    }
}

// ---------------- launch ----------------------------------------------------
extern "C" void kernel_launch(void* const* d_in, const int* in_sizes, int n_in,
                              void* d_out, int out_size) {
    const float* x = (const float*)d_in[0];   // [B, T, H]
    const float* Wx = (const float*)d_in[1];  // [L, 2, H, 4H]
    const float* Wh = (const float*)d_in[2];  // [L, 2, H, 4H]
    const float* b = (const float*)d_in[3];   // [L, 2, 4H]
    float* out = (float*)d_out;               // [B, T, 2H]

    const int smem_bytes = SM_WORDS * 4;  // 221184
    cudaFuncSetAttribute(lstm_persist_kernel<0>,
                         cudaFuncAttributeMaxDynamicSharedMemorySize, smem_bytes);
    cudaFuncSetAttribute(lstm_persist_kernel<1>,
                         cudaFuncAttributeMaxDynamicSharedMemorySize, smem_bytes);

    dim3 gx(G4 / 64, (TT * BB) / 64, 2);

    // ---- layer 0 ----  (anchor makes stream pos 3 = persist<0> for ncu -s 5)
    xproj_kernel<0><<<gx, 256>>>(x, Wx, b);
    init_state_kernel<<<256, 256>>>();
    profile_anchor_kernel<<<1, 32>>>();
    lstm_persist_kernel<0><<<NCTA, 512, smem_bytes>>>(Wh, nullptr);

    // ---- layer 1 ----
    xproj_kernel<1><<<gx, 256>>>(x, Wx, b);
    init_state_kernel<<<256, 256>>>();
    lstm_persist_kernel<1><<<NCTA, 512, smem_bytes>>>(Wh, out);
}

// round 10
// speedup vs baseline: 1.7175x; 1.1635x over previous
#include <cuda_runtime.h>
#include <cstdint>

#define BB 128
#define TT 256
#define HH 512
#define G4 2048  // 4*H
#define NCTA 128

// ---------------- scratch (device globals; no allocation allowed) ----------
__device__ float g_xproj[(size_t)2 * TT * BB * G4];  // [d][t][b][4H], scan order
__device__ float g_hout0[(size_t)2 * TT * BB * HH];  // layer-0 outputs [d][t][b][H]
__device__ float g_h[2][2][BB][HH];                  // [parity][d][b][h], tf32-pre-rounded
__device__ unsigned g_bar;                           // grid barrier counter

// ---------------- tf32 helpers --------------------------------------------
__device__ __forceinline__ uint32_t f2tf(float f) {
    uint32_t u;
    asm("cvt.rna.tf32.f32 %0, %1;" : "=r"(u) : "f"(f));  // round-to-nearest (unbiased)
    return u;
}

__device__ __forceinline__ void mma8(float* c, const uint32_t* a, const uint32_t* b) {
    asm volatile(
        "mma.sync.aligned.m16n8k8.row.col.f32.tf32.tf32.f32 "
        "{%0,%1,%2,%3}, {%4,%5,%6,%7}, {%8,%9}, {%0,%1,%2,%3};"
        : "+f"(c[0]), "+f"(c[1]), "+f"(c[2]), "+f"(c[3])
        : "r"(a[0]), "r"(a[1]), "r"(a[2]), "r"(a[3]), "r"(b[0]), "r"(b[1]));
}

__device__ __forceinline__ float sigm(float v) { return 1.0f / (1.0f + expf(-v)); }

__device__ __forceinline__ uint32_t smem_u32(const void* p) {
    uint32_t a;
    asm("{ .reg .u64 t; cvta.to.shared.u64 t, %1; cvt.u32.u64 %0, t; }"
        : "=r"(a) : "l"(p));
    return a;
}

// cp.async.cg: 16B, L1-bypass (L2-coherent with __stcg writers)
__device__ __forceinline__ void cp_async16(uint32_t dst, const void* src) {
    asm volatile("cp.async.cg.shared.global [%0], [%1], 16;" ::"r"(dst), "l"(src));
}
#define CP_COMMIT() asm volatile("cp.async.commit_group;" ::: "memory")
#define CP_WAIT0() asm volatile("cp.async.wait_group 0;" ::: "memory")
#define CP_WAIT1() asm volatile("cp.async.wait_group 1;" ::: "memory")

__device__ __forceinline__ void bar_arrive_release(unsigned* ctr) {
    asm volatile("red.release.gpu.global.add.u32 [%0], %1;" ::"l"(ctr), "r"(1u)
                 : "memory");
}
__device__ __forceinline__ unsigned bar_poll_acquire(unsigned* ctr) {
    unsigned v;
    asm volatile("ld.acquire.gpu.global.u32 %0, [%1];" : "=r"(v) : "l"(ctr)
                 : "memory");
    return v;
}

// ---------------- init: zero h (both parities) and barrier ------------------
__global__ void init_state_kernel() {
    int idx = blockIdx.x * blockDim.x + threadIdx.x;
    if (idx == 0) g_bar = 0;
    float4 z = make_float4(0.f, 0.f, 0.f, 0.f);
    if (idx < 65536) reinterpret_cast<float4*>(&g_h[0][0][0][0])[idx] = z;
}

// no-op: shifts stream launch index so ncu samples the persistent kernel
__global__ void profile_anchor_kernel() {}

// ---------------- input-projection GEMM v2 ----------------------------------
// R9: CTA tile 128x64, 8 warps m32n32 -> LDS/mma8 3.0 -> 2.0; tf32 cvt at STS
// (once per element; removes in-loop cvt ALU pressure). K chunks of 64,
// single-buffered (2 syncs/chunk as R2). Accumulation order per output is
// unchanged -> bit-identical to R2 xproj.
#define XP_SMEM (128 * 68 * 4 + 64 * 72 * 4)  // 53248 B (dynamic)

template <int LAYER>
__global__ void __launch_bounds__(256) xproj_kernel(const float* __restrict__ x,
                                                    const float* __restrict__ Wx_all,
                                                    const float* __restrict__ b_all) {
    extern __shared__ uint32_t xsm[];
    uint32_t* As = xsm;             // [128][68]
    uint32_t* Bs = xsm + 128 * 68;  // [64][72]

    const int d = blockIdx.z;
    const int n0 = blockIdx.x * 64;
    const int m0 = blockIdx.y * 128;
    const int tid = threadIdx.x;
    const int lane = tid & 31, wid = tid >> 5;
    const int wm = wid >> 1, wn = wid & 1;  // warp tile m32 x n32

    const float* Wx = Wx_all + (size_t)(LAYER * 2 + d) * HH * G4;

    float acc[2][4][4];
#pragma unroll
    for (int mt = 0; mt < 2; mt++)
#pragma unroll
        for (int nt = 0; nt < 4; nt++)
#pragma unroll
            for (int e = 0; e < 4; e++) acc[mt][nt][e] = 0.f;

    for (int k0 = 0; k0 < HH; k0 += 64) {
        __syncthreads();
        // stage A: 128 rows x 64 k, cvt at STS
#pragma unroll
        for (int w = 0; w < 8; w++) {
            int lin = w * 256 + tid;
            int row = lin >> 4;
            int kq = lin & 15;
            int rg = m0 + row;
            int tt = rg >> 7;
            int bb = rg & (BB - 1);
            const float* src;
            if (LAYER == 0) {
                int tsrc = d ? (TT - 1 - tt) : tt;
                src = x + ((size_t)bb * TT + tsrc) * HH + k0 + kq * 4;
            } else {
                src = g_hout0 + (((size_t)d * TT + tt) * BB + bb) * HH + k0 + kq * 4;
            }
            float4 v = *(const float4*)src;
            uint32_t* dst = &As[row * 68 + kq * 4];
            dst[0] = f2tf(v.x);
            dst[1] = f2tf(v.y);
            dst[2] = f2tf(v.z);
            dst[3] = f2tf(v.w);
        }
        // stage B: 64 k x 64 n, cvt at STS
#pragma unroll
        for (int w = 0; w < 4; w++) {
            int lin = w * 256 + tid;
            int kk = lin >> 4;
            int nq = lin & 15;
            float4 v = *(const float4*)&Wx[(size_t)(k0 + kk) * G4 + n0 + nq * 4];
            uint32_t* dst = &Bs[kk * 72 + nq * 4];
            dst[0] = f2tf(v.x);
            dst[1] = f2tf(v.y);
            dst[2] = f2tf(v.z);
            dst[3] = f2tf(v.w);
        }
        __syncthreads();
#pragma unroll
        for (int ks = 0; ks < 8; ks++) {
            int ak = ks * 8 + (lane & 3);
            uint32_t af[2][4], bf[4][2];
#pragma unroll
            for (int mt = 0; mt < 2; mt++) {
                int ar = wm * 32 + mt * 16 + (lane >> 2);
                af[mt][0] = As[ar * 68 + ak];
                af[mt][1] = As[(ar + 8) * 68 + ak];
                af[mt][2] = As[ar * 68 + ak + 4];
                af[mt][3] = As[(ar + 8) * 68 + ak + 4];
            }
#pragma unroll
            for (int nt = 0; nt < 4; nt++) {
                int bn = wn * 32 + nt * 8 + (lane >> 2);
                bf[nt][0] = Bs[ak * 72 + bn];
                bf[nt][1] = Bs[(ak + 4) * 72 + bn];
            }
#pragma unroll
            for (int mt = 0; mt < 2; mt++)
#pragma unroll
                for (int nt = 0; nt < 4; nt++) mma8(acc[mt][nt], af[mt], bf[nt]);
        }
    }
    const float* bias = b_all + (size_t)(LAYER * 2 + d) * G4;
#pragma unroll
    for (int mt = 0; mt < 2; mt++)
#pragma unroll
        for (int nt = 0; nt < 4; nt++) {
            int row = m0 + wm * 32 + mt * 16 + (lane >> 2);
            int col = n0 + wn * 32 + nt * 8 + 2 * (lane & 3);
            float b0v = bias[col], b1v = bias[col + 1];
            float* dst0 = g_xproj + ((size_t)d * TT * BB + row) * G4 + col;
            *(float2*)dst0 = make_float2(acc[mt][nt][0] + b0v, acc[mt][nt][1] + b1v);
            float* dst1 = g_xproj + ((size_t)d * TT * BB + row + 8) * G4 + col;
            *(float2*)dst1 = make_float2(acc[mt][nt][2] + b0v, acc[mt][nt][3] + b1v);
        }
}

// ---------------- persistent recurrence kernel ------------------------------
// 128 CTAs (64/dir), 512 threads / 16 warps, K-split (wk 0/1) as R8.
// R9: xproj slice prefetched into 8 regs at step top; output stores moved
// after barrier arrive (overlap the spin); red.release/ld.acquire barrier.
#define WH_STRIDE 40
#define PAC 68
#define ABW (128 * PAC)                       // words per buffer (8704)
#define AB_OFF (512 * WH_STRIDE)              // 20480 words
#define SM_WORDS (AB_OFF + 4 * ABW)           // 55296 words = 221184 B

template <int LAYER>
__global__ void __launch_bounds__(512, 1) lstm_persist_kernel(
    const float* __restrict__ Wh_all, float* __restrict__ out) {
    extern __shared__ uint32_t smw[];
    uint32_t* WhS = smw;                      // [512][40]
    uint32_t* Ab = smw + AB_OFF;              // [4][128][68]
    float* Gs0 = (float*)(smw + AB_OFF);              // overlay buf0, [128][40]
    float* Gs1 = (float*)(smw + AB_OFF + ABW);        // overlay buf1, [128][40]
    const uint32_t sbase = smem_u32(smw);

    const int tid = threadIdx.x;
    const int lane = tid & 31, wid = tid >> 5;
    const int wk = wid >> 3;          // K-half (0: k<256, 1: k>=256)
    const int wt = wid & 7;           // warp tile
    const int wm = wt >> 1, wn = wt & 1;
    const int d = blockIdx.x >> 6;
    const int h0 = (blockIdx.x & 63) * 8;

    const float* Wh = Wh_all + (size_t)(LAYER * 2 + d) * HH * G4;

    // ---- load Wh tile once, converted to tf32, gate strips packed n=g*8+hc
    for (int lin = tid; lin < 4096; lin += 512) {
        int k = lin >> 3;
        int q = lin & 7;
        int g = q >> 1;
        int part = (q & 1) * 4;
        float4 v = *(const float4*)&Wh[(size_t)k * G4 + g * HH + h0 + part];
        uint32_t* dst = &WhS[k * WH_STRIDE + g * 8 + part];
        dst[0] = f2tf(v.x);
        dst[1] = f2tf(v.y);
        dst[2] = f2tf(v.z);
        dst[3] = f2tf(v.w);
    }
    __syncthreads();

    const int phc = tid & 7;
    float c_reg[2] = {0.f, 0.f};

    for (int t = 0; t < TT; t++) {
        const float* hprev = &g_h[t & 1][d][0][0];
        const size_t xbase = ((size_t)d * TT * BB + (size_t)t * BB) * G4;

        // ---- prefetch this step's xproj slice into 8 regs (hidden by GEMM)
        float xpv[2][4];
#pragma unroll
        for (int e = 0; e < 2; e++) {
            int row = e * 64 + (tid >> 3);
            const float* xb = g_xproj + xbase + (size_t)row * G4 + h0 + phc;
            xpv[e][0] = __ldcg(xb);
            xpv[e][1] = __ldcg(xb + HH);
            xpv[e][2] = __ldcg(xb + 2 * HH);
            xpv[e][3] = __ldcg(xb + 3 * HH);
        }

        float acc[2][2][4];
#pragma unroll
        for (int mt = 0; mt < 2; mt++)
#pragma unroll
            for (int nt = 0; nt < 2; nt++)
#pragma unroll
                for (int e = 0; e < 4; e++) acc[mt][nt][e] = 0.f;

        // ---- prologue: G0 = {chunk0->buf0, chunk4->buf1}, G1 = {1->buf2, 5->buf3}
#pragma unroll
        for (int gph = 0; gph < 2; gph++) {
#pragma unroll
            for (int half = 0; half < 2; half++) {
                int ck = gph + half * 4;
                int bufi = gph * 2 + half;
#pragma unroll
                for (int w = 0; w < 4; w++) {
                    int p = w * 512 + tid;
                    int row = p >> 4, kq = p & 15;
                    uint32_t dst =
                        sbase + (AB_OFF + bufi * ABW + row * PAC + kq * 4) * 4;
                    cp_async16(dst, &hprev[(size_t)row * HH + ck * 64 + kq * 4]);
                }
            }
            CP_COMMIT();
        }

        // ---- 4 phases; phase p: wk0 computes chunk p, wk1 computes chunk p+4
#pragma unroll
        for (int p = 0; p < 4; p++) {
            if (p < 3) { CP_WAIT1(); } else { CP_WAIT0(); }
            __syncthreads();
            const uint32_t* Ac = &Ab[(((2 * p) & 3) + wk) * ABW];
            const int kb = wk * 256 + p * 64;
#pragma unroll
            for (int ks = 0; ks < 8; ks++) {
                uint32_t af[2][4], bfr[2][2];
                int ak = ks * 8 + (lane & 3);
                int ar = wm * 32 + (lane >> 2);
                af[0][0] = Ac[ar * PAC + ak];
                af[0][1] = Ac[(ar + 8) * PAC + ak];
                af[0][2] = Ac[ar * PAC + ak + 4];
                af[0][3] = Ac[(ar + 8) * PAC + ak + 4];
                af[1][0] = Ac[(ar + 16) * PAC + ak];
                af[1][1] = Ac[(ar + 24) * PAC + ak];
                af[1][2] = Ac[(ar + 16) * PAC + ak + 4];
                af[1][3] = Ac[(ar + 24) * PAC + ak + 4];
                int bk = kb + ks * 8 + (lane & 3);
                int bn = wn * 16 + (lane >> 2);
                bfr[0][0] = WhS[bk * WH_STRIDE + bn];
                bfr[0][1] = WhS[(bk + 4) * WH_STRIDE + bn];
                bfr[1][0] = WhS[bk * WH_STRIDE + bn + 8];
                bfr[1][1] = WhS[(bk + 4) * WH_STRIDE + bn + 8];
                mma8(acc[0][0], af[0], bfr[0]);
                mma8(acc[0][1], af[0], bfr[1]);
                mma8(acc[1][0], af[1], bfr[0]);
                mma8(acc[1][1], af[1], bfr[1]);
            }
            __syncthreads();
            if (p < 2) {
                int b0 = (2 * p) & 3;
#pragma unroll
                for (int half = 0; half < 2; half++) {
                    int ck = (p + 2) + half * 4;
#pragma unroll
                    for (int w = 0; w < 4; w++) {
                        int q = w * 512 + tid;
                        int row = q >> 4, kq = q & 15;
                        uint32_t dst =
                            sbase +
                            (AB_OFF + (b0 + half) * ABW + row * PAC + kq * 4) * 4;
                        cp_async16(dst,
                                   &hprev[(size_t)row * HH + ck * 64 + kq * 4]);
                    }
                }
                CP_COMMIT();
            }
        }

        // ---- stage partial accs (buf0/buf1 free: phase 3 read buf2/buf3)
        float* Gsw = wk ? Gs1 : Gs0;
#pragma unroll
        for (int mt = 0; mt < 2; mt++)
#pragma unroll
            for (int nt = 0; nt < 2; nt++) {
                int row = wm * 32 + mt * 16 + (lane >> 2);
                int col = wn * 16 + nt * 8 + 2 * (lane & 3);
                Gsw[row * 40 + col] = acc[mt][nt][0];
                Gsw[row * 40 + col + 1] = acc[mt][nt][1];
                Gsw[(row + 8) * 40 + col] = acc[mt][nt][2];
                Gsw[(row + 8) * 40 + col + 1] = acc[mt][nt][3];
            }
        __syncthreads();

        // ---- fused pointwise; write hnext only (inter-CTA critical path)
        float* hnext = &g_h[(t + 1) & 1][d][0][0];
        float hnv[2];
        int prow[2];
#pragma unroll
        for (int e = 0; e < 2; e++) {
            int row = e * 64 + (tid >> 3);
            prow[e] = row;
            float iv = Gs0[row * 40 + phc] + Gs1[row * 40 + phc] + xpv[e][0];
            float fv = Gs0[row * 40 + 8 + phc] + Gs1[row * 40 + 8 + phc] + xpv[e][1];
            float gv =
                Gs0[row * 40 + 16 + phc] + Gs1[row * 40 + 16 + phc] + xpv[e][2];
            float ov =
                Gs0[row * 40 + 24 + phc] + Gs1[row * 40 + 24 + phc] + xpv[e][3];
            float it = sigm(iv), ft = sigm(fv), gt = tanhf(gv), ot = sigm(ov);
            float cn = ft * c_reg[e] + it * gt;
            c_reg[e] = cn;
            float hn = ot * tanhf(cn);
            hnv[e] = hn;
            __stcg(&hnext[row * HH + h0 + phc], __uint_as_float(f2tf(hn)));
        }

        // ---- arrive early (release covers hnext via syncthreads cumulativity)
        __syncthreads();
        if (tid == 0) bar_arrive_release(&g_bar);

        // ---- output stores overlap the spin (not read by peers this step)
#pragma unroll
        for (int e = 0; e < 2; e++) {
            int row = prow[e];
            if (LAYER == 0) {
                g_hout0[(((size_t)d * TT + t) * BB + row) * HH + h0 + phc] = hnv[e];
            } else {
                int torig = d ? (TT - 1 - t) : t;
                out[((size_t)row * TT + torig) * (2 * HH) + (size_t)d * HH + h0 +
                    phc] = hnv[e];
            }
        }

        if (tid == 0) {
            unsigned target = (unsigned)NCTA * (unsigned)(t + 1);
            while (bar_poll_acquire(&g_bar) < target) {
            }
        }
        __syncthreads();
    }
}

// ---------------- launch ----------------------------------------------------
extern "C" void kernel_launch(void* const* d_in, const int* in_sizes, int n_in,
                              void* d_out, int out_size) {
    const float* x = (const float*)d_in[0];   // [B, T, H]
    const float* Wx = (const float*)d_in[1];  // [L, 2, H, 4H]
    const float* Wh = (const float*)d_in[2];  // [L, 2, H, 4H]
    const float* b = (const float*)d_in[3];   // [L, 2, 4H]
    float* out = (float*)d_out;               // [B, T, 2H]

    const int smem_bytes = SM_WORDS * 4;  // 221184
    cudaFuncSetAttribute(lstm_persist_kernel<0>,
                         cudaFuncAttributeMaxDynamicSharedMemorySize, smem_bytes);
    cudaFuncSetAttribute(lstm_persist_kernel<1>,
                         cudaFuncAttributeMaxDynamicSharedMemorySize, smem_bytes);
    cudaFuncSetAttribute(xproj_kernel<0>,
                         cudaFuncAttributeMaxDynamicSharedMemorySize, XP_SMEM);
    cudaFuncSetAttribute(xproj_kernel<1>,
                         cudaFuncAttributeMaxDynamicSharedMemorySize, XP_SMEM);

    dim3 gx(G4 / 64, (TT * BB) / 128, 2);

    // ---- layer 0 ----  (anchor keeps stream pos aligned for ncu sampling)
    xproj_kernel<0><<<gx, 256, XP_SMEM>>>(x, Wx, b);
    init_state_kernel<<<256, 256>>>();
    profile_anchor_kernel<<<1, 32>>>();
    lstm_persist_kernel<0><<<NCTA, 512, smem_bytes>>>(Wh, nullptr);

    // ---- layer 1 ----
    xproj_kernel<1><<<gx, 256, XP_SMEM>>>(x, Wx, b);
    init_state_kernel<<<256, 256>>>();
    lstm_persist_kernel<1><<<NCTA, 512, smem_bytes>>>(Wh, out);
}